// round 11
// baseline (speedup 1.0000x reference)
#include <cuda_runtime.h>

// Problem shape (fixed by the reference's setup_inputs):
//   data: (B=8, T=500, C=306) f32      locs: (B=8, C=306, 2) f32
//   out:  (B, T, 100, 100) f32 = gather of nearest channel per grid bin.
#define NB   8
#define NT   500
#define NC   306
#define NCP  308         // NC padded to multiple of 4 (sentinel channels)
#define NG   100
#define NG2  10000
#define TCHUNK 10        // t rows per gather block: 12.2 KB smem -> occ 100%

// Scratch: nearest-channel index per (b, g). Static device global (no allocs).
__device__ int g_idx[NB * NG2];

// ---------------------------------------------------------------------------
// Kernel 1: idx[b,g] = argmin_c d2(g,c), bit-exact vs the XLA-CPU reference
// (chain validated rel_err = 0.0 since R6):
//   a_c  = rn( rn(lx*lx) + rn(ly*ly) )
//   dot  = rn( rn(gx*lx) + rn(gy*ly) )     (no fma)
//   d2   = rn( rn(a_c + bg) - 2*dot )      (2*dot exact; via pre-doubled locs:
//                                           pow2 scaling commutes with rn)
// 4 lanes cooperate on one g (part = lane%4, channels c = 4k+part):
//   - serial compare chain 306 -> 77 iters,
//   - warp LDS per iter = 4 consecutive float4 (64 B), conflict-free,
//   - 1256 blocks -> no wave-quantization tail.
// Sentinel channels (a = 3e38) never win under strict '<'. Cross-part combine
// is lexicographic (d2, idx), reproducing jnp.argmin first-index tie-break.
// ---------------------------------------------------------------------------
__global__ __launch_bounds__(256)
void argmin_kernel(const float* __restrict__ locs) {
    __shared__ float4 s_lca[NCP];   // (2*lx, 2*ly, |l|^2, 0)

    const int b = blockIdx.y;
    const float* L = locs + (size_t)b * NC * 2;

    for (int c = threadIdx.x; c < NCP; c += blockDim.x) {
        if (c < NC) {
            float lx = L[2 * c + 0];
            float ly = L[2 * c + 1];
            float a  = __fadd_rn(__fmul_rn(lx, lx), __fmul_rn(ly, ly));
            s_lca[c] = make_float4(__fmul_rn(2.0f, lx),   // exact
                                   __fmul_rn(2.0f, ly),   // exact
                                   a, 0.0f);
        } else {
            s_lca[c] = make_float4(0.0f, 0.0f, 3.0e38f, 0.0f);  // sentinel
        }
    }
    __syncthreads();

    const int part = threadIdx.x & 3;
    const int g    = blockIdx.x * 64 + (threadIdx.x >> 2);  // <= 10047, safe

    const int   igx = g / NG;
    const int   igy = g - igx * NG;
    const float gx  = (float)igx;
    const float gy  = (float)igy;
    const float bg  = gx * gx + gy * gy;   // integer-exact (< 2^24)

    float best = 3.0e38f;
    int   bi   = 0x3fffffff;
    #pragma unroll 7
    for (int k = 0; k < NCP / 4; ++k) {    // 77 iterations
        const int c = 4 * k + part;
        float4 v  = s_lca[c];
        float  px = __fmul_rn(gx, v.x);         // 2*rn(gx*lx)
        float  py = __fmul_rn(gy, v.y);         // 2*rn(gy*ly)
        float  dd = __fadd_rn(px, py);          // 2*rn(px'+py')  (exact x2)
        float  t1 = __fadd_rn(v.z, bg);
        float  d2 = __fadd_rn(t1, -dd);         // rn(t1 - 2*dot)
        if (d2 < best) { best = d2; bi = c; }
    }

    // Combine the 4 parts: lexicographic (d2, idx) min over the lane quad.
    #pragma unroll
    for (int off = 1; off <= 2; off <<= 1) {
        float od = __shfl_xor_sync(0xffffffffu, best, off);
        int   oi = __shfl_xor_sync(0xffffffffu, bi,   off);
        if (od < best || (od == best && oi < bi)) { best = od; bi = oi; }
    }

    if (part == 0 && g < NG2)
        g_idx[b * NG2 + g] = bi;
}

// ---------------------------------------------------------------------------
// Kernel 2: out[b,t,g] = data[b,t,idx[b,g]]   -- L1-throughput-bound.
// Block = (b, 10-row t-chunk, 1024 consecutive g), 256 threads, 12.2 KB smem
// -> 16 blocks/SM (64-warp cap). Software-pipelined t-loop: iteration t+1's
// four LDS gathers are issued before iteration t's STG.128, hiding LDS
// latency behind the store instead of serializing (R9: issue=10.6%).
// idx4 prefetched via LDG before staging so its latency hides under the
// staging loop + barrier. __stcs: 160 MB output, don't write-allocate L2.
// ---------------------------------------------------------------------------
__global__ __launch_bounds__(256)
void gather_kernel(const float* __restrict__ data,
                   float* __restrict__ out) {
    __shared__ __align__(16) float s_data[TCHUNK * NC];   // 12240 B

    const int b    = blockIdx.z;
    const int slot = blockIdx.x * blockDim.x + threadIdx.x;  // group of 4 g
    const int t0   = blockIdx.y * TCHUNK;
    const bool active = slot < (NG2 / 4);

    // Prefetch indices (LDG) before staging: latency overlaps the barrier.
    int4 idx4 = make_int4(0, 0, 0, 0);
    if (active)
        idx4 = reinterpret_cast<const int4*>(g_idx + b * NG2)[slot];

    // Stage 10 contiguous data rows (3060 floats = 765 float4; offsets
    // (b*500+t0)*306 with t0 % 10 == 0 are multiples of 4 -> aligned).
    const float4* src = reinterpret_cast<const float4*>(
        data + (size_t)(b * NT + t0) * NC);
    #pragma unroll
    for (int i = threadIdx.x; i < (TCHUNK * NC) / 4; i += 256)
        reinterpret_cast<float4*>(s_data)[i] = src[i];
    __syncthreads();

    if (active) {
        const float* srow = s_data;
        float*       orow = out + (size_t)(b * NT + t0) * NG2
                                + (size_t)slot * 4;
        float4 v;
        v.x = srow[idx4.x];
        v.y = srow[idx4.y];
        v.z = srow[idx4.z];
        v.w = srow[idx4.w];
        #pragma unroll
        for (int t = 0; t < TCHUNK - 1; ++t) {
            const float* nrow = srow + NC;
            float4 n;                       // prefetch t+1 before storing t
            n.x = nrow[idx4.x];
            n.y = nrow[idx4.y];
            n.z = nrow[idx4.z];
            n.w = nrow[idx4.w];
            __stcs(reinterpret_cast<float4*>(orow), v);
            v = n;
            srow = nrow;
            orow += NG2;
        }
        __stcs(reinterpret_cast<float4*>(orow), v);
    }
}

// ---------------------------------------------------------------------------
extern "C" void kernel_launch(void* const* d_in, const int* in_sizes, int n_in,
                              void* d_out, int out_size) {
    // metadata order: data (1,224,000 f32), locs (4,896 f32). Select by size
    // to be robust to ordering.
    const float* data = (const float*)d_in[0];
    const float* locs = (const float*)d_in[1];
    if (n_in >= 2 && in_sizes[0] < in_sizes[1]) {
        data = (const float*)d_in[1];
        locs = (const float*)d_in[0];
    }
    float* out = (float*)d_out;

    // Phase 1: nearest-channel index per (b, g). 4 lanes per bin.
    {
        dim3 grid((NG2 + 63) / 64, NB, 1);         // (157, 8) = 1256 blocks
        argmin_kernel<<<grid, 256>>>(locs);
    }
    // Phase 2: gather.
    {
        const int gx = (NG2 / 4 + 255) / 256;      // 10 blocks of 256 slots
        dim3 grid(gx, NT / TCHUNK, NB);             // (10, 50, 8) = 4000 blocks
        gather_kernel<<<grid, 256>>>(data, out);
    }
    (void)out_size;
}